// round 3
// baseline (speedup 1.0000x reference)
#include <cuda_runtime.h>
#include <cuda_bf16.h>

// Output [B,2] = stack([p, 1-p]) where p = sigmoid(evs · fc3_w + fc3_b) and
// evs comes ONLY from the 4-qubit circuit (q_params, q_basis). The CNN branch
// (x, conv*, fc1, fc2) is dead code in the reference — its activations are
// never consumed by the logits. So we simulate the 16-amplitude state vector
// in one thread and broadcast the scalar result.

struct C2 { float r, i; };

__device__ __forceinline__ C2 cmul(C2 a, C2 b) {
    return { a.r * b.r - a.i * b.i, a.r * b.i + a.i * b.r };
}
__device__ __forceinline__ C2 cadd(C2 a, C2 b) { return { a.r + b.r, a.i + b.i }; }

// Apply a 2x2 gate on wire w (stride 8>>w in the flat 16-amp state).
__device__ __forceinline__ void gate1(C2* st, int w, C2 U00, C2 U01, C2 U10, C2 U11) {
    const int s = 8 >> w;
    #pragma unroll
    for (int i = 0; i < 16; i++) {
        if (i & s) continue;
        C2 a = st[i];
        C2 b = st[i + s];
        st[i]     = cadd(cmul(U00, a), cmul(U01, b));
        st[i + s] = cadd(cmul(U10, a), cmul(U11, b));
    }
}

__device__ __forceinline__ void apply_rx(C2* st, int w, float t) {
    float c, s;
    __sincosf(0.5f * t, &s, &c);
    // use accurate versions for safety
    c = cosf(0.5f * t); s = sinf(0.5f * t);
    gate1(st, w, {c, 0.f}, {0.f, -s}, {0.f, -s}, {c, 0.f});
}
__device__ __forceinline__ void apply_ry(C2* st, int w, float t) {
    float c = cosf(0.5f * t), s = sinf(0.5f * t);
    gate1(st, w, {c, 0.f}, {-s, 0.f}, {s, 0.f}, {c, 0.f});
}
__device__ __forceinline__ void apply_rz(C2* st, int w, float t) {
    float c = cosf(0.5f * t), s = sinf(0.5f * t);
    // diag(e^{-it/2}, e^{+it/2})
    gate1(st, w, {c, -s}, {0.f, 0.f}, {0.f, 0.f}, {c, s});
}

__global__ __launch_bounds__(1024, 1)
void qhbc_kernel(const float* __restrict__ q_params,  // [2,4,3]
                 const float* __restrict__ q_basis,   // [4,3]
                 const float* __restrict__ fc3_w,     // [1,4]
                 const float* __restrict__ fc3_b,     // [1]
                 float* __restrict__ out,             // [B,2]
                 int B) {
    __shared__ float s_p;

    if (threadIdx.x == 0) {
        C2 st[16];
        #pragma unroll
        for (int i = 0; i < 16; i++) st[i] = {0.f, 0.f};
        st[0] = {1.f, 0.f};

        // Basis rotations: rx, ry, rz per wire
        #pragma unroll
        for (int w = 0; w < 4; w++) {
            apply_rx(st, w, q_basis[w * 3 + 0]);
            apply_ry(st, w, q_basis[w * 3 + 1]);
            apply_rz(st, w, q_basis[w * 3 + 2]);
        }

        // DEPTH=2 layers: rotations per wire then CNOT chain
        #pragma unroll
        for (int l = 0; l < 2; l++) {
            #pragma unroll
            for (int w = 0; w < 4; w++) {
                const float* p = q_params + (l * 4 + w) * 3;
                apply_rx(st, w, p[0]);
                apply_ry(st, w, p[1]);
                apply_rz(st, w, p[2]);
            }
            // CNOT(control=w, target=w+1) for w = 0..2
            #pragma unroll
            for (int w = 0; w < 3; w++) {
                const int sc = 8 >> w;        // control stride
                const int sg = 8 >> (w + 1);  // target stride
                #pragma unroll
                for (int i = 0; i < 16; i++) {
                    if ((i & sc) && !(i & sg)) {
                        C2 t = st[i];
                        st[i] = st[i | sg];
                        st[i | sg] = t;
                    }
                }
            }
        }

        // Z expectation per wire: sum |amp|^2 * (+1 if bit=0 else -1)
        float evs[4] = {0.f, 0.f, 0.f, 0.f};
        #pragma unroll
        for (int i = 0; i < 16; i++) {
            float pr = st[i].r * st[i].r + st[i].i * st[i].i;
            #pragma unroll
            for (int w = 0; w < 4; w++) {
                evs[w] += ((i >> (3 - w)) & 1) ? -pr : pr;
            }
        }

        float logit = fc3_b[0];
        #pragma unroll
        for (int w = 0; w < 4; w++) logit += evs[w] * fc3_w[w];

        s_p = 1.f / (1.f + expf(-logit));
    }

    __syncthreads();
    const float p = s_p;
    const float q = 1.f - p;
    for (int i = threadIdx.x; i < B; i += blockDim.x) {
        out[2 * i + 0] = p;
        out[2 * i + 1] = q;
    }
}

extern "C" void kernel_launch(void* const* d_in, const int* in_sizes, int n_in,
                              void* d_out, int out_size) {
    // metadata order: 0=x 1=conv1_w 2=conv1_b 3=conv2_w 4=conv2_b 5=fc1_w
    //                 6=fc1_b 7=fc2_w 8=fc2_b 9=q_params 10=q_basis 11=fc3_w 12=fc3_b
    const float* q_params = (const float*)d_in[9];
    const float* q_basis  = (const float*)d_in[10];
    const float* fc3_w    = (const float*)d_in[11];
    const float* fc3_b    = (const float*)d_in[12];
    float* out = (float*)d_out;
    const int B = out_size / 2;

    qhbc_kernel<<<1, 1024>>>(q_params, q_basis, fc3_w, fc3_b, out, B);
}

// round 4
// speedup vs baseline: 4.2419x; 4.2419x over previous
#include <cuda_runtime.h>
#include <cuda_bf16.h>

// Output [B,2] = [p, 1-p], p = sigmoid(evs . fc3_w + fc3_b); evs depends only
// on the 4-qubit circuit (q_params, q_basis). CNN branch is dead code.
//
// R3: warp-parallel state-vector sim.
//  - lanes 0..11 each build one merged SU(2) gate U = Rz*Ry*Rx (__sincosf)
//  - lanes 0..15 hold one amplitude each; gates applied via __shfl_xor
//  - SU(2) structure: U = [[u0, u1], [-conj(u1), conj(u0)]], so the per-lane
//    row selection is just two sign flips on (u0.i, u1.r).

__global__ __launch_bounds__(1024, 1)
void qhbc_kernel(const float* __restrict__ q_params,  // [2,4,3]
                 const float* __restrict__ q_basis,   // [4,3]
                 const float* __restrict__ fc3_w,     // [1,4]
                 const float* __restrict__ fc3_b,     // [1]
                 float2* __restrict__ out,            // [B] of (p, 1-p)
                 int B) {
    __shared__ float sU[12][4];      // u0.r, u0.i, u1.r, u1.i per merged gate
    __shared__ float s_probs[16];
    __shared__ float s_p;

    const int tid = threadIdx.x;

    if (tid < 32) {
        const int lane = tid;

        // ---- Phase 1: lanes 0..11 build merged gates (parallel) ----
        // Slot g: wire w = g&3. Slots 0..3 = basis, 4..11 = params (l*4+w = g-4).
        if (lane < 12) {
            const int w = lane & 3;
            const float* ang = (lane < 4) ? (q_basis + w * 3)
                                          : (q_params + (lane - 4) * 3);
            float sa, ca, sb, cb, sc, cc;
            __sincosf(0.5f * ang[0], &sa, &ca);   // Rx
            __sincosf(0.5f * ang[1], &sb, &cb);   // Ry
            __sincosf(0.5f * ang[2], &sc, &cc);   // Rz
            // M = Ry*Rx, row 0:
            //   M00 = (cb*ca,  sb*sa),  M01 = (-sb*ca, -cb*sa)
            const float m00r =  cb * ca, m00i =  sb * sa;
            const float m01r = -sb * ca, m01i = -cb * sa;
            // U row0 = (cc - i*sc) * M row0  (row1 implied by SU(2) structure)
            sU[lane][0] = cc * m00r + sc * m00i;  // u0.r
            sU[lane][1] = cc * m00i - sc * m00r;  // u0.i
            sU[lane][2] = cc * m01r + sc * m01i;  // u1.r
            sU[lane][3] = cc * m01i - sc * m01r;  // u1.i
        }
        __syncwarp();

        // ---- Phase 2: 16-amplitude sim, one amp per lane ----
        // amp index = lane; wire w occupies bit (8>>w).
        float sr = (lane == 0) ? 1.f : 0.f;
        float si = 0.f;

#define GATE(g, w) {                                                         \
        const int s_ = 8 >> (w);                                             \
        const float u0r = sU[g][0], u0i = sU[g][1];                          \
        const float u1r = sU[g][2], u1i = sU[g][3];                          \
        const float sgn = (lane & s_) ? -1.f : 1.f;                          \
        const float Ai = sgn * u0i, Br = sgn * u1r;                          \
        const float pr = __shfl_xor_sync(0xffffffffu, sr, s_);               \
        const float pi = __shfl_xor_sync(0xffffffffu, si, s_);               \
        const float nr = u0r * sr - Ai * si + Br * pr - u1i * pi;            \
        const float ni = u0r * si + Ai * sr + Br * pi + u1i * pr;            \
        sr = nr; si = ni; }

#define CNOT(w) {                                                            \
        const int sc_ = 8 >> (w), sg_ = 4 >> (w);                            \
        const float pr = __shfl_xor_sync(0xffffffffu, sr, sg_);              \
        const float pi = __shfl_xor_sync(0xffffffffu, si, sg_);              \
        if (lane & sc_) { sr = pr; si = pi; } }

        // basis rotations
        GATE(0, 0) GATE(1, 1) GATE(2, 2) GATE(3, 3)
        // layer 0
        GATE(4, 0) GATE(5, 1) GATE(6, 2) GATE(7, 3)
        CNOT(0) CNOT(1) CNOT(2)
        // layer 1
        GATE(8, 0) GATE(9, 1) GATE(10, 2) GATE(11, 3)
        CNOT(0) CNOT(1) CNOT(2)

#undef GATE
#undef CNOT

        // ---- Phase 3: measurement + head ----
        const float prob = sr * sr + si * si;
        if (lane < 16) s_probs[lane] = prob;
        __syncwarp();

        if (lane == 0) {
            float e0 = 0.f, e1 = 0.f, e2 = 0.f, e3 = 0.f;
            #pragma unroll
            for (int i = 0; i < 16; i++) {
                const float pr = s_probs[i];
                e0 += (i & 8) ? -pr : pr;   // wire 0 -> bit 3
                e1 += (i & 4) ? -pr : pr;   // wire 1 -> bit 2
                e2 += (i & 2) ? -pr : pr;   // wire 2 -> bit 1
                e3 += (i & 1) ? -pr : pr;   // wire 3 -> bit 0
            }
            const float logit = fc3_b[0] + e0 * fc3_w[0] + e1 * fc3_w[1]
                                         + e2 * fc3_w[2] + e3 * fc3_w[3];
            s_p = 1.f / (1.f + __expf(-logit));
        }
    }

    __syncthreads();

    // ---- Broadcast: 1024 threads, one float2 (STG.64) each ----
    const float p = s_p;
    const float q = 1.f - p;
    for (int i = tid; i < B; i += blockDim.x) {
        out[i] = make_float2(p, q);
    }
}

extern "C" void kernel_launch(void* const* d_in, const int* in_sizes, int n_in,
                              void* d_out, int out_size) {
    // metadata order: 0=x 1=conv1_w 2=conv1_b 3=conv2_w 4=conv2_b 5=fc1_w
    //                 6=fc1_b 7=fc2_w 8=fc2_b 9=q_params 10=q_basis 11=fc3_w 12=fc3_b
    const float* q_params = (const float*)d_in[9];
    const float* q_basis  = (const float*)d_in[10];
    const float* fc3_w    = (const float*)d_in[11];
    const float* fc3_b    = (const float*)d_in[12];
    float2* out = (float2*)d_out;
    const int B = out_size / 2;

    qhbc_kernel<<<1, 1024>>>(q_params, q_basis, fc3_w, fc3_b, out, B);
}